// round 9
// baseline (speedup 1.0000x reference)
#include <cuda_runtime.h>
#include <cuda_fp16.h>
#include <math.h>

#define N_NODES   100000
#define N_EDGES   1600000
#define N_FEAT    50
#define HIDDEN    16
#define N_CLASSES 10
#define CAP       64           // bucket capacity; deg ~ Poisson(16), P(>=64)~2e-18
#define E8        (N_EDGES / 8)

typedef unsigned long long ull;

// ---- packed f32x2 helpers (sm_103a) ----
__device__ __forceinline__ ull pk2(float lo, float hi) {
    ull r;
    asm("mov.b64 %0, {%1, %2};" : "=l"(r) : "f"(lo), "f"(hi));
    return r;
}
__device__ __forceinline__ void upk2(float& lo, float& hi, ull v) {
    asm("mov.b64 {%0, %1}, %2;" : "=f"(lo), "=f"(hi) : "l"(v));
}
__device__ __forceinline__ ull fma2(ull a, ull b, ull c) {
    ull d;
    asm("fma.rn.f32x2 %0, %1, %2, %3;" : "=l"(d) : "l"(a), "l"(b), "l"(c));
    return d;
}

// ---- scratch (static device globals; zero-initialized at load) ----
__device__ int   g_cnt[N_NODES];              // bucket fill counts (reset by agg2)
__device__ float g_dinv[N_NODES];
__device__ __align__(16) int g_csrp[N_NODES * CAP];  // padded bucket CSR (src ids)
__device__ __align__(16) float  g_xw0[N_NODES * HIDDEN];   // x@w1_0 + b1 (fp32)
__device__ __align__(16) __half g_xp1h[N_NODES * HIDDEN];  // fp16 x@w1_1 (scaled later)
__device__ __align__(16) float  g_hw [N_NODES * HIDDEN];   // h@w2_0 + b2 (fp32)
__device__ __align__(16) __half g_hph[N_NODES * HIDDEN];   // fp16 dinv*(h@w2_1)

// ---- K1: fused thread-role kernel: scatter 8 edges THEN project one node ----
// Phases are data-independent; proj FMAs fill scatter's atomic-latency shadow.
// proj writes UNSCALED xp1 (cnt is concurrently mutated; dinv applied in k_scale).
__global__ void __launch_bounds__(256, 6)
k_fusedSP(const int* __restrict__ ei,
          const float* __restrict__ x,
          const float* __restrict__ w0,
          const float* __restrict__ w1,
          const float* __restrict__ b1) {
    __shared__ ull sw0p[N_FEAT * HIDDEN / 2];
    __shared__ ull sw1p[N_FEAT * HIDDEN / 2];
    __shared__ float sb[HIDDEN];
    for (int i = threadIdx.x; i < N_FEAT * HIDDEN; i += blockDim.x) {
        ((float*)sw0p)[i] = w0[i];
        ((float*)sw1p)[i] = w1[i];
    }
    if (threadIdx.x < HIDDEN) sb[threadIdx.x] = b1[threadIdx.x];
    __syncthreads();

    int gid = blockIdx.x * blockDim.x + threadIdx.x;

    // ---- scatter phase ----
    if (gid < E8) {
        const int4* sp = (const int4*)ei;
        const int4* dp = (const int4*)(ei + N_EDGES);
        int4 s0 = sp[gid * 2], s1 = sp[gid * 2 + 1];
        int4 d0 = dp[gid * 2], d1 = dp[gid * 2 + 1];
        int p0 = atomicAdd(&g_cnt[d0.x], 1);
        int p1 = atomicAdd(&g_cnt[d0.y], 1);
        int p2 = atomicAdd(&g_cnt[d0.z], 1);
        int p3 = atomicAdd(&g_cnt[d0.w], 1);
        int p4 = atomicAdd(&g_cnt[d1.x], 1);
        int p5 = atomicAdd(&g_cnt[d1.y], 1);
        int p6 = atomicAdd(&g_cnt[d1.z], 1);
        int p7 = atomicAdd(&g_cnt[d1.w], 1);
        if (p0 < CAP) g_csrp[d0.x * CAP + p0] = s0.x;
        if (p1 < CAP) g_csrp[d0.y * CAP + p1] = s0.y;
        if (p2 < CAP) g_csrp[d0.z * CAP + p2] = s0.z;
        if (p3 < CAP) g_csrp[d0.w * CAP + p3] = s0.w;
        if (p4 < CAP) g_csrp[d1.x * CAP + p4] = s1.x;
        if (p5 < CAP) g_csrp[d1.y * CAP + p5] = s1.y;
        if (p6 < CAP) g_csrp[d1.z * CAP + p6] = s1.z;
        if (p7 < CAP) g_csrp[d1.w * CAP + p7] = s1.w;
    }

    // ---- projection phase (unscaled) ----
    int n = gid;
    if (n >= N_NODES) return;

    const float2* xr = (const float2*)(x + (size_t)n * N_FEAT);  // 50 even
    ull z = pk2(0.0f, 0.0f);

    // pass 1: a0 = x @ w1_0  (8 packed accumulators)
    {
        ull a0[8];
#pragma unroll
        for (int p = 0; p < 8; p++) a0[p] = z;
#pragma unroll 5
        for (int k2 = 0; k2 < N_FEAT / 2; k2++) {
            float2 xv = __ldg(&xr[k2]);
            ull xa = pk2(xv.x, xv.x);
            ull xb = pk2(xv.y, xv.y);
            const ull* wa = sw0p + (2 * k2) * 8;
#pragma unroll
            for (int p = 0; p < 8; p++) {
                a0[p] = fma2(xa, wa[p],     a0[p]);
                a0[p] = fma2(xb, wa[8 + p], a0[p]);
            }
        }
        float4* o0 = (float4*)(g_xw0 + (size_t)n * HIDDEN);
#pragma unroll
        for (int q = 0; q < 4; q++) {
            float va, vb, vc, vd;
            upk2(va, vb, a0[q * 2]);
            upk2(vc, vd, a0[q * 2 + 1]);
            float4 r;
            r.x = va + sb[q * 4 + 0];
            r.y = vb + sb[q * 4 + 1];
            r.z = vc + sb[q * 4 + 2];
            r.w = vd + sb[q * 4 + 3];
            o0[q] = r;
        }
    }
    // pass 2: a1 = x @ w1_1 (x row re-read from L1)
    {
        ull a1[8];
#pragma unroll
        for (int p = 0; p < 8; p++) a1[p] = z;
#pragma unroll 5
        for (int k2 = 0; k2 < N_FEAT / 2; k2++) {
            float2 xv = __ldg(&xr[k2]);
            ull xa = pk2(xv.x, xv.x);
            ull xb = pk2(xv.y, xv.y);
            const ull* wa = sw1p + (2 * k2) * 8;
#pragma unroll
            for (int p = 0; p < 8; p++) {
                a1[p] = fma2(xa, wa[p],     a1[p]);
                a1[p] = fma2(xb, wa[8 + p], a1[p]);
            }
        }
        __half2 hx[8];
#pragma unroll
        for (int p = 0; p < 8; p++) {
            float va, vb;
            upk2(va, vb, a1[p]);
            hx[p] = __floats2half2_rn(va, vb);
        }
        uint4* oh = (uint4*)(g_xp1h + (size_t)n * HIDDEN);
        oh[0] = *(uint4*)&hx[0];
        oh[1] = *(uint4*)&hx[4];
    }
}

// ---- K2: dinv from final cnt; scale xp1h in place ----
__global__ void k_scale() {
    int n = blockIdx.x * blockDim.x + threadIdx.x;
    if (n >= N_NODES) return;
    int d = g_cnt[n];
    float dn = (d > 0) ? rsqrtf((float)d) : 0.0f;
    g_dinv[n] = dn;
    uint4* p = (uint4*)(g_xp1h + (size_t)n * HIDDEN);
    uint4 v0 = p[0], v1 = p[1];
    __half2* h0 = (__half2*)&v0;
    __half2* h1 = (__half2*)&v1;
#pragma unroll
    for (int i = 0; i < 4; i++) {
        float2 f = __half22float2(h0[i]);
        h0[i] = __floats2half2_rn(dn * f.x, dn * f.y);
        f = __half22float2(h1[i]);
        h1[i] = __floats2half2_rn(dn * f.x, dn * f.y);
    }
    p[0] = v0;
    p[1] = v1;
}

// fp16 gather accumulate: v holds 4 half2 (8 channels)
__device__ __forceinline__ void acc_h8(float2* ac, uint4 v) {
    float2 f;
    f = __half22float2(*(__half2*)&v.x); ac[0].x += f.x; ac[0].y += f.y;
    f = __half22float2(*(__half2*)&v.y); ac[1].x += f.x; ac[1].y += f.y;
    f = __half22float2(*(__half2*)&v.z); ac[2].x += f.x; ac[2].y += f.y;
    f = __half22float2(*(__half2*)&v.w); ac[3].x += f.x; ac[3].y += f.y;
}

// shared gather loop: int4 idx loads over this node's bucket
__device__ __forceinline__ void gather_bucket(const uint4* __restrict__ pay,
                                              int node, int q, int len,
                                              float2* ac) {
    const int4* ip = (const int4*)(g_csrp + node * CAP);   // 16B-aligned
    int n4 = len >> 2;
#pragma unroll 2
    for (int i = 0; i < n4; i++) {
        int4 s = __ldg(&ip[i]);
        uint4 v0 = __ldg(&pay[s.x * 2 + q]);
        uint4 v1 = __ldg(&pay[s.y * 2 + q]);
        uint4 v2 = __ldg(&pay[s.z * 2 + q]);
        uint4 v3 = __ldg(&pay[s.w * 2 + q]);
        acc_h8(ac, v0); acc_h8(ac, v1); acc_h8(ac, v2); acc_h8(ac, v3);
    }
    for (int j = n4 * 4; j < len; j++) {
        int s = __ldg(&g_csrp[node * CAP + j]);
        acc_h8(ac, __ldg(&pay[s * 2 + q]));
    }
}

// ---- K3: fused layer-1 agg + relu + layer-2 proj. 2 lanes/node ----
__global__ void k_agg1p2(const float* __restrict__ w0,
                         const float* __restrict__ w1,
                         const float* __restrict__ b2) {
    __shared__ float sw0[HIDDEN][HIDDEN];   // [k][c], cols 10..15 = 0
    __shared__ float sw1[HIDDEN][HIDDEN];
    __shared__ float sb[HIDDEN];
    int t = threadIdx.x;
    {
        int k = t >> 4, c = t & 15;
        sw0[k][c] = (c < N_CLASSES) ? w0[k * N_CLASSES + c] : 0.0f;
        sw1[k][c] = (c < N_CLASSES) ? w1[k * N_CLASSES + c] : 0.0f;
    }
    if (t < HIDDEN) sb[t] = (t < N_CLASSES) ? b2[t] : 0.0f;
    __syncthreads();

    int gid  = blockIdx.x * blockDim.x + t;   // N_NODES*2 threads (guarded)
    int node = gid >> 1;
    int q    = gid & 1;
    if (node >= N_NODES) return;

    int len = g_cnt[node];
    float2 ac[4] = {{0.f,0.f},{0.f,0.f},{0.f,0.f},{0.f,0.f}};
    gather_bucket((const uint4*)g_xp1h, node, q, len, ac);

    float dn = g_dinv[node];
    const float4* xw = (const float4*)g_xw0;
    float4 f0 = xw[node * 4 + q * 2];
    float4 f1 = xw[node * 4 + q * 2 + 1];
    float h[8];
    h[0] = fmaxf(f0.x + dn * ac[0].x, 0.0f);
    h[1] = fmaxf(f0.y + dn * ac[0].y, 0.0f);
    h[2] = fmaxf(f0.z + dn * ac[1].x, 0.0f);
    h[3] = fmaxf(f0.w + dn * ac[1].y, 0.0f);
    h[4] = fmaxf(f1.x + dn * ac[2].x, 0.0f);
    h[5] = fmaxf(f1.y + dn * ac[2].y, 0.0f);
    h[6] = fmaxf(f1.z + dn * ac[3].x, 0.0f);
    h[7] = fmaxf(f1.w + dn * ac[3].y, 0.0f);

    // layer-2 projection: channels q*8..q*8+7 ; h[k] via width-2 shuffle
    float A0[8], A1[8];
    int cb = q * 8;
#pragma unroll
    for (int i = 0; i < 8; i++) { A0[i] = sb[cb + i]; A1[i] = 0.0f; }
#pragma unroll
    for (int k = 0; k < HIDDEN; k++) {
        float hk = __shfl_sync(0xffffffffu, h[k & 7], k >> 3, 2);
#pragma unroll
        for (int i = 0; i < 8; i++) {
            A0[i] = fmaf(hk, sw0[k][cb + i], A0[i]);
            A1[i] = fmaf(hk, sw1[k][cb + i], A1[i]);
        }
    }
    float4* hw = (float4*)g_hw;
    float4 o0, o1;
    o0.x = A0[0]; o0.y = A0[1]; o0.z = A0[2]; o0.w = A0[3];
    o1.x = A0[4]; o1.y = A0[5]; o1.z = A0[6]; o1.w = A0[7];
    hw[node * 4 + q * 2]     = o0;
    hw[node * 4 + q * 2 + 1] = o1;
    __half2 hp[4];
#pragma unroll
    for (int i = 0; i < 4; i++)
        hp[i] = __floats2half2_rn(dn * A1[2 * i], dn * A1[2 * i + 1]);
    ((uint4*)g_hph)[node * 2 + q] = *(uint4*)&hp[0];
}

// ---- K4: layer-2 aggregation + log_softmax; resets cnt for next replay ----
__global__ void k_agg2(float* __restrict__ out) {
    int gid  = blockIdx.x * blockDim.x + threadIdx.x;
    int node = gid >> 1;
    int q    = gid & 1;
    if (node >= N_NODES) return;

    int len = g_cnt[node];
    if (q == 0) g_cnt[node] = 0;          // replay-idempotent
    float2 ac[4] = {{0.f,0.f},{0.f,0.f},{0.f,0.f},{0.f,0.f}};
    gather_bucket((const uint4*)g_hph, node, q, len, ac);

    float dn = g_dinv[node];
    const float4* hwv = (const float4*)g_hw;
    float4 f0 = hwv[node * 4 + q * 2];
    float4 f1 = hwv[node * 4 + q * 2 + 1];
    float L[8];
    L[0] = f0.x + dn * ac[0].x;
    L[1] = f0.y + dn * ac[0].y;
    L[2] = f0.z + dn * ac[1].x;
    L[3] = f0.w + dn * ac[1].y;
    L[4] = f1.x + dn * ac[2].x;
    L[5] = f1.y + dn * ac[2].y;
    L[6] = f1.z + dn * ac[3].x;
    L[7] = f1.w + dn * ac[3].y;

    // valid channels: lane 0 -> c0..7 (all), lane 1 -> c8,c9 (i<2)
    int nvalid = q ? 2 : 8;
    float m = -1e30f;
#pragma unroll
    for (int i = 0; i < 8; i++) if (i < nvalid) m = fmaxf(m, L[i]);
    m = fmaxf(m, __shfl_xor_sync(0xffffffffu, m, 1, 2));
    float s = 0.0f;
#pragma unroll
    for (int i = 0; i < 8; i++) if (i < nvalid) s += expf(L[i] - m);
    s += __shfl_xor_sync(0xffffffffu, s, 1, 2);
    float lse = m + logf(s);

    float* op = out + (size_t)node * N_CLASSES;
    if (q == 0) {
#pragma unroll
        for (int i = 0; i < 4; i++)
            ((float2*)op)[i] = make_float2(L[2 * i] - lse, L[2 * i + 1] - lse);
    } else {
        ((float2*)(op + 8))[0] = make_float2(L[0] - lse, L[1] - lse);
    }
}

extern "C" void kernel_launch(void* const* d_in, const int* in_sizes, int n_in,
                              void* d_out, int out_size) {
    const float* x    = (const float*)d_in[0];
    const int*   ei   = (const int*)d_in[1];     // int32: JAX x64 disabled
    const float* w1_0 = (const float*)d_in[2];
    const float* w1_1 = (const float*)d_in[3];
    const float* b1   = (const float*)d_in[4];
    const float* w2_0 = (const float*)d_in[5];
    const float* w2_1 = (const float*)d_in[6];
    const float* b2   = (const float*)d_in[7];
    float* out = (float*)d_out;

    const int FB = (E8 + 255) / 256;             // 782 (covers nodes too)
    const int PB = (N_NODES + 255) / 256;        // 391
    const int GA = (N_NODES * 2 + 255) / 256;    // 782
    k_fusedSP<<<FB, 256>>>(ei, x, w1_0, w1_1, b1);
    k_scale  <<<PB, 256>>>();
    k_agg1p2 <<<GA, 256>>>(w2_0, w2_1, b2);
    k_agg2   <<<GA, 256>>>(out);
}